// round 1
// baseline (speedup 1.0000x reference)
#include <cuda_runtime.h>
#include <cuda_bf16.h>

#define FULL 0xffffffffu

// Per-warp histogram update: match lanes with equal idx, elected leader does a
// plain (non-atomic) shared RMW — leaders of distinct values hit distinct
// addresses, and invalid lanes carry a sentinel that never stores.
__device__ __forceinline__ void hupd(unsigned* hw, int base, int idx,
                                     bool valid, int lane) {
    unsigned m = __match_any_sync(FULL, idx);
    int leader = __ffs(m) - 1;
    if (valid && lane == leader) {
        hw[base + idx] += (unsigned)__popc(m);
    }
}

__global__ void __launch_bounds__(128)
mlp_row_kernel(const float* __restrict__ cont_p, const float* __restrict__ cont_c,
               const int* __restrict__ cat_p, const int* __restrict__ cat_c,
               const int* __restrict__ lengths,
               const float* __restrict__ w_p1, const float* __restrict__ b_p1,
               const float* __restrict__ w_p2, const float* __restrict__ b_p2,
               const float* __restrict__ w_c1, const float* __restrict__ b_c1,
               const float* __restrict__ w_c2, const float* __restrict__ b_c2,
               const float* __restrict__ emb_gender, const float* __restrict__ emb_korean,
               const float* __restrict__ emb_primary, const float* __restrict__ emb_job,
               const float* __restrict__ emb_rep, const float* __restrict__ emb_place,
               const float* __restrict__ emb_add,
               const float* __restrict__ w_fc1, const float* __restrict__ b_fc1,
               const float* __restrict__ w_fc2, const float* __restrict__ b_fc2,
               float* __restrict__ out, int S)
{
    // Histogram value layout (101 counters total):
    // gender@0(2) korean@2(2) primary@4(2) job@6(11) rep@17(34) place@51(19) add@70(31)
    __shared__ unsigned hist_s[4 * 104];   // per-warp privatized
    __shared__ float accp_s[128];
    __shared__ float accc_s[128];
    __shared__ float cntf_s[104];
    __shared__ float us_s[64];             // pooled pre-activations: u_p[0:32], u_c[32:64]
    __shared__ float pooled_s[128];        // [ep | ec | hp | hc]
    __shared__ float h_s[64];

    const int tid  = threadIdx.x;
    const int lane = tid & 31;
    const int w    = tid >> 5;
    const int b    = blockIdx.x;
    const int len  = lengths[b];
    const int rowbase = b * S;

    for (int i = tid; i < 4 * 104; i += 128) hist_s[i] = 0u;

    // lane = output channel d; first-layer weights live in registers
    const float wp0  = w_p1[lane];
    const float wp1v = w_p1[32 + lane];
    const float wp2v = w_p1[64 + lane];
    const float bp   = b_p1[lane];
    const float wc0  = w_c1[lane];
    const float wc1v = w_c1[32 + lane];
    const float bc   = b_c1[lane];

    __syncthreads();

    float accp = 0.f, accc = 0.f;
    unsigned* hw = &hist_s[w * 104];

    // Each warp takes 32-token chunks, strided by 4 warps; only the valid prefix.
    for (int t0 = w * 32; t0 < len; t0 += 128) {
        const int nv = min(32, len - t0);
        const int t  = t0 + lane;
        const bool valid = lane < nv;

        float p0 = 0.f, p1 = 0.f, p2 = 0.f, c0 = 0.f, c1 = 0.f;
        int i0 = 999, i1 = 999, i2 = 999, i3 = 999, i4 = 999, j0 = 999, j1 = 999;
        if (valid) {
            const float* cp = cont_p + (rowbase + t) * 3;
            p0 = cp[0]; p1 = cp[1]; p2 = cp[2];
            float2 cc = *reinterpret_cast<const float2*>(cont_c + (rowbase + t) * 2);
            c0 = cc.x; c1 = cc.y;
            const int* ip = cat_p + (rowbase + t) * 5;
            i0 = ip[0]; i1 = ip[1]; i2 = ip[2]; i3 = ip[3]; i4 = ip[4];
            int2 jc = *reinterpret_cast<const int2*>(cat_c + (rowbase + t) * 2);
            j0 = jc.x; j1 = jc.y;
        }

        // Category histograms (warp-aggregated, no atomics)
        hupd(hw, 0,  i0, valid, lane);
        hupd(hw, 2,  i1, valid, lane);
        hupd(hw, 4,  i2, valid, lane);
        hupd(hw, 6,  i3, valid, lane);
        hupd(hw, 17, i4, valid, lane);
        hupd(hw, 51, j0, valid, lane);
        hupd(hw, 70, j1, valid, lane);

        // Continuous-feature first layers: broadcast token j's scalars,
        // every lane computes its channel, accumulates the post-relu sum.
        #pragma unroll 4
        for (int j = 0; j < nv; j++) {
            float a0 = __shfl_sync(FULL, p0, j);
            float a1 = __shfl_sync(FULL, p1, j);
            float a2 = __shfl_sync(FULL, p2, j);
            float a3 = __shfl_sync(FULL, c0, j);
            float a4 = __shfl_sync(FULL, c1, j);
            float tp = fmaf(a2, wp2v, fmaf(a1, wp1v, fmaf(a0, wp0, bp)));
            accp += fmaxf(tp, 0.f);
            float tc = fmaf(a4, wc1v, fmaf(a3, wc0, bc));
            accc += fmaxf(tc, 0.f);
        }
    }

    accp_s[tid] = accp;
    accc_s[tid] = accc;
    __syncthreads();

    if (tid < 101) {
        cntf_s[tid] = (float)(hist_s[tid] + hist_s[104 + tid] +
                              hist_s[208 + tid] + hist_s[312 + tid]);
    }
    __syncthreads();

    const float invlen = 1.0f / (float)len;
    const int d = lane;

    if (w == 0) {
        // u_p = mean(relu(...)); hp = u_p @ W_p2 + b_p2
        float u = (accp_s[d] + accp_s[32 + d] + accp_s[64 + d] + accp_s[96 + d]) * invlen;
        us_s[d] = u;
        __syncwarp();
        float acc = b_p2[d];
        #pragma unroll
        for (int e = 0; e < 32; e++) acc = fmaf(us_s[e], w_p2[e * 32 + d], acc);
        pooled_s[64 + d] = acc;
    } else if (w == 1) {
        float u = (accc_s[d] + accc_s[32 + d] + accc_s[64 + d] + accc_s[96 + d]) * invlen;
        us_s[32 + d] = u;
        __syncwarp();
        float acc = b_c2[d];
        #pragma unroll
        for (int e = 0; e < 32; e++) acc = fmaf(us_s[32 + e], w_c2[e * 32 + d], acc);
        pooled_s[96 + d] = acc;
    } else if (w == 2) {
        // ep = (sum over 5 tables of count-weighted rows) / (5 * len)
        float s = 0.f;
        #pragma unroll
        for (int v = 0; v < 2; v++)  s = fmaf(cntf_s[v],      emb_gender[v * 32 + d], s);
        #pragma unroll
        for (int v = 0; v < 2; v++)  s = fmaf(cntf_s[2 + v],  emb_korean[v * 32 + d], s);
        #pragma unroll
        for (int v = 0; v < 2; v++)  s = fmaf(cntf_s[4 + v],  emb_primary[v * 32 + d], s);
        #pragma unroll
        for (int v = 0; v < 11; v++) s = fmaf(cntf_s[6 + v],  emb_job[v * 32 + d], s);
        #pragma unroll
        for (int v = 0; v < 34; v++) s = fmaf(cntf_s[17 + v], emb_rep[v * 32 + d], s);
        pooled_s[d] = s * invlen * 0.2f;
    } else {
        float s = 0.f;
        #pragma unroll
        for (int v = 0; v < 19; v++) s = fmaf(cntf_s[51 + v], emb_place[v * 32 + d], s);
        #pragma unroll
        for (int v = 0; v < 31; v++) s = fmaf(cntf_s[70 + v], emb_add[v * 32 + d], s);
        pooled_s[32 + d] = s * invlen * 0.5f;
    }
    __syncthreads();

    // fc1: 128 -> 64, relu
    if (tid < 64) {
        float acc = b_fc1[tid];
        #pragma unroll 8
        for (int i = 0; i < 128; i++)
            acc = fmaf(pooled_s[i], w_fc1[i * 64 + tid], acc);
        h_s[tid] = fmaxf(acc, 0.f);
    }
    __syncthreads();

    // fc2: 64 -> 2, relu (warp 0, tree reduce)
    if (w == 0) {
        float h0 = h_s[lane], h1 = h_s[32 + lane];
        float s0 = h0 * w_fc2[lane * 2]     + h1 * w_fc2[(32 + lane) * 2];
        float s1 = h0 * w_fc2[lane * 2 + 1] + h1 * w_fc2[(32 + lane) * 2 + 1];
        #pragma unroll
        for (int off = 16; off; off >>= 1) {
            s0 += __shfl_xor_sync(FULL, s0, off);
            s1 += __shfl_xor_sync(FULL, s1, off);
        }
        if (lane == 0) {
            out[b * 2]     = fmaxf(s0 + b_fc2[0], 0.f);
            out[b * 2 + 1] = fmaxf(s1 + b_fc2[1], 0.f);
        }
    }
}

extern "C" void kernel_launch(void* const* d_in, const int* in_sizes, int n_in,
                              void* d_out, int out_size)
{
    const float* cont_p   = (const float*)d_in[0];
    const float* cont_c   = (const float*)d_in[1];
    const int*   cat_p    = (const int*)  d_in[2];
    const int*   cat_c    = (const int*)  d_in[3];
    const int*   lengths  = (const int*)  d_in[4];
    const float* w_p1     = (const float*)d_in[5];
    const float* b_p1     = (const float*)d_in[6];
    const float* w_p2     = (const float*)d_in[7];
    const float* b_p2     = (const float*)d_in[8];
    const float* w_c1     = (const float*)d_in[9];
    const float* b_c1     = (const float*)d_in[10];
    const float* w_c2     = (const float*)d_in[11];
    const float* b_c2     = (const float*)d_in[12];
    const float* emb_gender  = (const float*)d_in[13];
    const float* emb_korean  = (const float*)d_in[14];
    const float* emb_primary = (const float*)d_in[15];
    const float* emb_job     = (const float*)d_in[16];
    const float* emb_rep     = (const float*)d_in[17];
    const float* emb_place   = (const float*)d_in[18];
    const float* emb_add     = (const float*)d_in[19];
    const float* w_fc1    = (const float*)d_in[20];
    const float* b_fc1    = (const float*)d_in[21];
    const float* w_fc2    = (const float*)d_in[22];
    const float* b_fc2    = (const float*)d_in[23];
    float* out = (float*)d_out;

    const int B = in_sizes[4];                 // lengths: [B]
    const int S = in_sizes[0] / (B * 3);       // cont_p: [B,S,3]

    mlp_row_kernel<<<B, 128>>>(cont_p, cont_c, cat_p, cat_c, lengths,
                               w_p1, b_p1, w_p2, b_p2, w_c1, b_c1, w_c2, b_c2,
                               emb_gender, emb_korean, emb_primary, emb_job,
                               emb_rep, emb_place, emb_add,
                               w_fc1, b_fc1, w_fc2, b_fc2, out, S);
}

// round 3
// speedup vs baseline: 1.1220x; 1.1220x over previous
#include <cuda_runtime.h>
#include <cuda_bf16.h>

#define FULL 0xffffffffu

// ---- packed f32x2 helpers (Blackwell; FFMA2 only reachable via PTX) ----
__device__ __forceinline__ unsigned long long pk2(float lo, float hi) {
    unsigned long long r;
    asm("mov.b64 %0, {%1, %2};" : "=l"(r) : "f"(lo), "f"(hi));
    return r;
}
__device__ __forceinline__ unsigned long long fma2(unsigned long long a,
                                                   unsigned long long b,
                                                   unsigned long long c) {
    unsigned long long r;
    asm("fma.rn.f32x2 %0, %1, %2, %3;" : "=l"(r) : "l"(a), "l"(b), "l"(c));
    return r;
}
__device__ __forceinline__ void upk2(unsigned long long v, float& lo, float& hi) {
    asm("mov.b64 {%0, %1}, %2;" : "=f"(lo), "=f"(hi) : "l"(v));
}

// Per-warp histogram update: match lanes with equal idx, elected leader does a
// plain (non-atomic) shared RMW — leaders of distinct values hit distinct
// addresses, and invalid lanes carry a sentinel that never stores.
__device__ __forceinline__ void hupd(unsigned* hw, int base, int idx,
                                     bool valid, int lane) {
    unsigned m = __match_any_sync(FULL, idx);
    int leader = __ffs(m) - 1;
    if (valid && lane == leader) {
        hw[base + idx] += (unsigned)__popc(m);
    }
}

__global__ void __launch_bounds__(128)
mlp_row_kernel(const float* __restrict__ cont_p, const float* __restrict__ cont_c,
               const int* __restrict__ cat_p, const int* __restrict__ cat_c,
               const int* __restrict__ lengths,
               const float* __restrict__ w_p1, const float* __restrict__ b_p1,
               const float* __restrict__ w_p2, const float* __restrict__ b_p2,
               const float* __restrict__ w_c1, const float* __restrict__ b_c1,
               const float* __restrict__ w_c2, const float* __restrict__ b_c2,
               const float* __restrict__ emb_gender, const float* __restrict__ emb_korean,
               const float* __restrict__ emb_primary, const float* __restrict__ emb_job,
               const float* __restrict__ emb_rep, const float* __restrict__ emb_place,
               const float* __restrict__ emb_add,
               const float* __restrict__ w_fc1, const float* __restrict__ b_fc1,
               const float* __restrict__ w_fc2, const float* __restrict__ b_fc2,
               float* __restrict__ out, int S)
{
    // Histogram value layout (101 counters total):
    // gender@0(2) korean@2(2) primary@4(2) job@6(11) rep@17(34) place@51(19) add@70(31)
    __shared__ unsigned hist_s[4 * 104];   // per-warp privatized
    __shared__ float accp_s[128];
    __shared__ float accc_s[128];
    __shared__ float cntf_s[104];
    __shared__ float us_s[64];             // pooled pre-activations: u_p[0:32], u_c[32:64]
    __shared__ float pooled_s[128];        // [ep | ec | hp | hc]
    __shared__ float h_s[64];
    __shared__ float4 stageX[4][2][32];    // per-warp double-buffered: (p0, c0, p1, c1)
    __shared__ float2 stageY[4][2][32];    // per-warp double-buffered: (p2, 0)

    const int tid  = threadIdx.x;
    const int lane = tid & 31;
    const int w    = tid >> 5;
    const int b    = blockIdx.x;
    const int len  = lengths[b];
    const int rowbase = b * S;

    for (int i = tid; i < 4 * 104; i += 128) hist_s[i] = 0u;

    // lane = output channel d; first-layer weights packed (p-side, c-side) per lane
    const unsigned long long wA = pk2(w_p1[lane],      w_c1[lane]);       // (wp0, wc0)
    const unsigned long long wB = pk2(w_p1[32 + lane], w_c1[32 + lane]);  // (wp1, wc1)
    const unsigned long long wC = pk2(w_p1[64 + lane], 0.f);              // (wp2, 0)
    const unsigned long long bias2 = pk2(b_p1[lane], b_c1[lane]);

    __syncthreads();

    float accp = 0.f, accc = 0.f;
    unsigned* hw = &hist_s[w * 104];
    int buf = 0;

    // Each warp takes 32-token chunks, strided by 4 warps; only the valid prefix.
    for (int t0 = w * 32; t0 < len; t0 += 128, buf ^= 1) {
        const int nv = min(32, len - t0);
        const int t  = t0 + lane;
        const bool valid = lane < nv;

        int i0 = 999, i1 = 999, i2 = 999, i3 = 999, i4 = 999, j0 = 999, j1 = 999;
        if (valid) {
            const float* cp = cont_p + (rowbase + t) * 3;
            float p0 = cp[0], p1 = cp[1], p2 = cp[2];
            float2 cc = *reinterpret_cast<const float2*>(cont_c + (rowbase + t) * 2);
            const int* ip = cat_p + (rowbase + t) * 5;
            i0 = ip[0]; i1 = ip[1]; i2 = ip[2]; i3 = ip[3]; i4 = ip[4];
            int2 jc = *reinterpret_cast<const int2*>(cat_c + (rowbase + t) * 2);
            j0 = jc.x; j1 = jc.y;
            stageX[w][buf][lane] = make_float4(p0, cc.x, p1, cc.y);
            stageY[w][buf][lane] = make_float2(p2, 0.f);
        }

        // Category histograms (warp-aggregated, no atomics)
        hupd(hw, 0,  i0, valid, lane);
        hupd(hw, 2,  i1, valid, lane);
        hupd(hw, 4,  i2, valid, lane);
        hupd(hw, 6,  i3, valid, lane);
        hupd(hw, 17, i4, valid, lane);
        hupd(hw, 51, j0, valid, lane);
        hupd(hw, 70, j1, valid, lane);

        __syncwarp();

        // Continuous-feature first layers: LDS.128/LDS.64 broadcast token j,
        // every lane computes its (p, c) channel pair via packed FFMA2.
        #pragma unroll 8
        for (int j = 0; j < nv; j++) {
            float4 x = stageX[w][buf][j];
            float2 y = stageY[w][buf][j];
            unsigned long long a01 = pk2(x.x, x.y);   // (p0, c0)
            unsigned long long a23 = pk2(x.z, x.w);   // (p1, c1)
            unsigned long long ayy = pk2(y.x, y.y);   // (p2, 0)
            unsigned long long tpc = fma2(a01, wA, bias2);
            tpc = fma2(a23, wB, tpc);
            tpc = fma2(ayy, wC, tpc);
            float tp, tc;
            upk2(tpc, tp, tc);
            accp += fmaxf(tp, 0.f);
            accc += fmaxf(tc, 0.f);
        }
        // no trailing sync: next chunk writes the other stage buffer
    }

    accp_s[tid] = accp;
    accc_s[tid] = accc;
    __syncthreads();

    if (tid < 101) {
        cntf_s[tid] = (float)(hist_s[tid] + hist_s[104 + tid] +
                              hist_s[208 + tid] + hist_s[312 + tid]);
    }
    __syncthreads();

    const float invlen = 1.0f / (float)len;
    const int d = lane;

    if (w == 0) {
        // u_p = mean(relu(...)); hp = u_p @ W_p2 + b_p2
        float u = (accp_s[d] + accp_s[32 + d] + accp_s[64 + d] + accp_s[96 + d]) * invlen;
        us_s[d] = u;
        __syncwarp();
        float acc = b_p2[d];
        #pragma unroll
        for (int e = 0; e < 32; e++) acc = fmaf(us_s[e], w_p2[e * 32 + d], acc);
        pooled_s[64 + d] = acc;
    } else if (w == 1) {
        float u = (accc_s[d] + accc_s[32 + d] + accc_s[64 + d] + accc_s[96 + d]) * invlen;
        us_s[32 + d] = u;
        __syncwarp();
        float acc = b_c2[d];
        #pragma unroll
        for (int e = 0; e < 32; e++) acc = fmaf(us_s[32 + e], w_c2[e * 32 + d], acc);
        pooled_s[96 + d] = acc;
    } else if (w == 2) {
        // ep = (sum over 5 tables of count-weighted rows) / (5 * len)
        float s = 0.f;
        #pragma unroll
        for (int v = 0; v < 2; v++)  s = fmaf(cntf_s[v],      emb_gender[v * 32 + d], s);
        #pragma unroll
        for (int v = 0; v < 2; v++)  s = fmaf(cntf_s[2 + v],  emb_korean[v * 32 + d], s);
        #pragma unroll
        for (int v = 0; v < 2; v++)  s = fmaf(cntf_s[4 + v],  emb_primary[v * 32 + d], s);
        #pragma unroll
        for (int v = 0; v < 11; v++) s = fmaf(cntf_s[6 + v],  emb_job[v * 32 + d], s);
        #pragma unroll
        for (int v = 0; v < 34; v++) s = fmaf(cntf_s[17 + v], emb_rep[v * 32 + d], s);
        pooled_s[d] = s * invlen * 0.2f;
    } else {
        float s = 0.f;
        #pragma unroll
        for (int v = 0; v < 19; v++) s = fmaf(cntf_s[51 + v], emb_place[v * 32 + d], s);
        #pragma unroll
        for (int v = 0; v < 31; v++) s = fmaf(cntf_s[70 + v], emb_add[v * 32 + d], s);
        pooled_s[32 + d] = s * invlen * 0.5f;
    }
    __syncthreads();

    // fc1: 128 -> 64, relu
    if (tid < 64) {
        float acc = b_fc1[tid];
        #pragma unroll 8
        for (int i = 0; i < 128; i++)
            acc = fmaf(pooled_s[i], w_fc1[i * 64 + tid], acc);
        h_s[tid] = fmaxf(acc, 0.f);
    }
    __syncthreads();

    // fc2: 64 -> 2, relu (warp 0, tree reduce)
    if (w == 0) {
        float h0 = h_s[lane], h1 = h_s[32 + lane];
        float s0 = h0 * w_fc2[lane * 2]     + h1 * w_fc2[(32 + lane) * 2];
        float s1 = h0 * w_fc2[lane * 2 + 1] + h1 * w_fc2[(32 + lane) * 2 + 1];
        #pragma unroll
        for (int off = 16; off; off >>= 1) {
            s0 += __shfl_xor_sync(FULL, s0, off);
            s1 += __shfl_xor_sync(FULL, s1, off);
        }
        if (lane == 0) {
            out[b * 2]     = fmaxf(s0 + b_fc2[0], 0.f);
            out[b * 2 + 1] = fmaxf(s1 + b_fc2[1], 0.f);
        }
    }
}

extern "C" void kernel_launch(void* const* d_in, const int* in_sizes, int n_in,
                              void* d_out, int out_size)
{
    const float* cont_p   = (const float*)d_in[0];
    const float* cont_c   = (const float*)d_in[1];
    const int*   cat_p    = (const int*)  d_in[2];
    const int*   cat_c    = (const int*)  d_in[3];
    const int*   lengths  = (const int*)  d_in[4];
    const float* w_p1     = (const float*)d_in[5];
    const float* b_p1     = (const float*)d_in[6];
    const float* w_p2     = (const float*)d_in[7];
    const float* b_p2     = (const float*)d_in[8];
    const float* w_c1     = (const float*)d_in[9];
    const float* b_c1     = (const float*)d_in[10];
    const float* w_c2     = (const float*)d_in[11];
    const float* b_c2     = (const float*)d_in[12];
    const float* emb_gender  = (const float*)d_in[13];
    const float* emb_korean  = (const float*)d_in[14];
    const float* emb_primary = (const float*)d_in[15];
    const float* emb_job     = (const float*)d_in[16];
    const float* emb_rep     = (const float*)d_in[17];
    const float* emb_place   = (const float*)d_in[18];
    const float* emb_add     = (const float*)d_in[19];
    const float* w_fc1    = (const float*)d_in[20];
    const float* b_fc1    = (const float*)d_in[21];
    const float* w_fc2    = (const float*)d_in[22];
    const float* b_fc2    = (const float*)d_in[23];
    float* out = (float*)d_out;

    const int B = in_sizes[4];                 // lengths: [B]
    const int S = in_sizes[0] / (B * 3);       // cont_p: [B,S,3]

    mlp_row_kernel<<<B, 128>>>(cont_p, cont_c, cat_p, cat_c, lengths,
                               w_p1, b_p1, w_p2, b_p2, w_c1, b_c1, w_c2, b_c2,
                               emb_gender, emb_korean, emb_primary, emb_job,
                               emb_rep, emb_place, emb_add,
                               w_fc1, b_fc1, w_fc2, b_fc2, out, S);
}